// round 1
// baseline (speedup 1.0000x reference)
#include <cuda_runtime.h>
#include <cuda_bf16.h>

#define D_MODEL   768
#define N_HEADS_C 12
#define HEAD_DIM  64
#define S_LEN     4096
#define BATCH     2
#define N_TOK     (BATCH * S_LEN)     // 8192
#define PADL      68                  // smem row pad: conflict-free + 16B aligned

// Scratch (allocation-free rule: __device__ globals)
__device__ float g_Q[BATCH * N_HEADS_C * S_LEN * HEAD_DIM];
__device__ float g_K[BATCH * N_HEADS_C * S_LEN * HEAD_DIM];
__device__ float g_V[BATCH * N_HEADS_C * S_LEN * HEAD_DIM];
__device__ float g_ctx[N_TOK * D_MODEL];

// ---------------------------------------------------------------------------
// QKV projection: x[8192,768] @ W[768,768] -> scatter to [B,H,S,Dh]
// blockIdx.z in {0,1,2} selects (Wq->g_Q, Wk->g_K, Wv->g_V)
// ---------------------------------------------------------------------------
__global__ __launch_bounds__(256)
void qkv_gemm_kernel(const float* __restrict__ x,
                     const float* __restrict__ Wq,
                     const float* __restrict__ Wk,
                     const float* __restrict__ Wv) {
    __shared__ float As[8][128];   // transposed [k][m]
    __shared__ float Bs[8][128];   // [k][n]

    const int z = blockIdx.z;
    const float* W = (z == 0) ? Wq : ((z == 1) ? Wk : Wv);
    float* dst = (z == 0) ? g_Q : ((z == 1) ? g_K : g_V);

    const int m0 = blockIdx.y * 128;
    const int n0 = blockIdx.x * 128;
    const int tid = threadIdx.x;
    const int tx = tid & 15, ty = tid >> 4;
    const int ar = tid >> 1, ac = (tid & 1) * 4;
    const int br = tid >> 5, bc = (tid & 31) * 4;

    float acc[8][8];
#pragma unroll
    for (int i = 0; i < 8; i++)
#pragma unroll
        for (int j = 0; j < 8; j++) acc[i][j] = 0.0f;

    for (int k0 = 0; k0 < D_MODEL; k0 += 8) {
        float4 av = *(const float4*)(x + (size_t)(m0 + ar) * D_MODEL + k0 + ac);
        As[ac + 0][ar] = av.x;
        As[ac + 1][ar] = av.y;
        As[ac + 2][ar] = av.z;
        As[ac + 3][ar] = av.w;
        float4 bv = *(const float4*)(W + (size_t)(k0 + br) * D_MODEL + n0 + bc);
        *(float4*)&Bs[br][bc] = bv;
        __syncthreads();
#pragma unroll
        for (int kk = 0; kk < 8; kk++) {
            float a[8], b[8];
            *(float4*)(a)     = *(const float4*)&As[kk][ty * 8];
            *(float4*)(a + 4) = *(const float4*)&As[kk][ty * 8 + 4];
            *(float4*)(b)     = *(const float4*)&Bs[kk][tx * 8];
            *(float4*)(b + 4) = *(const float4*)&Bs[kk][tx * 8 + 4];
#pragma unroll
            for (int i = 0; i < 8; i++)
#pragma unroll
                for (int j = 0; j < 8; j++) acc[i][j] += a[i] * b[j];
        }
        __syncthreads();
    }

    // Scatter epilogue into [B,H,S,Dh]
#pragma unroll
    for (int i = 0; i < 8; i++) {
        const int m = m0 + ty * 8 + i;
        const int b = m >> 12;            // /4096
        const int s = m & (S_LEN - 1);
#pragma unroll
        for (int j = 0; j < 8; j += 4) {
            const int n = n0 + tx * 8 + j;
            const int h = n >> 6;
            const int d = n & 63;
            float4 o = make_float4(acc[i][j], acc[i][j + 1], acc[i][j + 2], acc[i][j + 3]);
            *(float4*)(dst + ((size_t)((b * N_HEADS_C + h) * S_LEN + s)) * HEAD_DIM + d) = o;
        }
    }
}

// ---------------------------------------------------------------------------
// Flash attention fp32, causal. 64x64 tiles, 256 threads, 4x4 per thread.
// Dynamic smem: Qs[64][68] (r,d) | KP[64][68] (K^T [d][k], reused as P [r][k]) | Vs[64][68] (k,d)
// ---------------------------------------------------------------------------
__global__ __launch_bounds__(256)
void attn_kernel() {
    extern __shared__ float sm[];
    float* Qs = sm;                  // row-major [r][d], pre-scaled by 1/8
    float* KP = sm + 64 * PADL;      // K^T [d][k] -> P [r][k]
    float* Vs = sm + 2 * 64 * PADL;  // [k][d]

    const int bh = blockIdx.y;                              // 0..23
    const int qt = (int)gridDim.x - 1 - (int)blockIdx.x;    // heavy tiles first
    const size_t base = (size_t)bh * S_LEN * HEAD_DIM;
    const float* Qg = g_Q + base + (size_t)qt * 64 * HEAD_DIM;
    const float* Kg = g_K + base;
    const float* Vg = g_V + base;

    const int tid = threadIdx.x;
    const int tx = tid & 15, ty = tid >> 4;

    // Load Q tile, fold softmax scale 1/sqrt(64)=0.125
#pragma unroll
    for (int i = tid; i < 64 * 16; i += 256) {
        const int r = i >> 4, c4 = (i & 15) << 2;
        float4 q = *(const float4*)(Qg + r * HEAD_DIM + c4);
        float* dp = Qs + r * PADL + c4;
        dp[0] = q.x * 0.125f; dp[1] = q.y * 0.125f;
        dp[2] = q.z * 0.125f; dp[3] = q.w * 0.125f;
    }

    float m_i[4], l_i[4], O[4][4];
#pragma unroll
    for (int i = 0; i < 4; i++) {
        m_i[i] = -1e30f; l_i[i] = 0.0f;
#pragma unroll
        for (int j = 0; j < 4; j++) O[i][j] = 0.0f;
    }

    for (int kt = 0; kt <= qt; kt++) {
        __syncthreads();   // previous P/V reads complete before overwrite
        const float* Kt = Kg + (size_t)kt * 64 * HEAD_DIM;
        const float* Vt = Vg + (size_t)kt * 64 * HEAD_DIM;
#pragma unroll
        for (int i = tid; i < 64 * 16; i += 256) {
            const int k = i >> 4, c4 = (i & 15) << 2;
            float4 kv = *(const float4*)(Kt + k * HEAD_DIM + c4);
            KP[(c4 + 0) * PADL + k] = kv.x;
            KP[(c4 + 1) * PADL + k] = kv.y;
            KP[(c4 + 2) * PADL + k] = kv.z;
            KP[(c4 + 3) * PADL + k] = kv.w;
            float4 vv = *(const float4*)(Vt + k * HEAD_DIM + c4);
            *(float4*)(Vs + k * PADL + c4) = vv;
        }
        __syncthreads();

        // Scores: acc[i][j] = sum_d Q[4ty+i][d] * K[4tx+j][d]  (pre-scaled)
        float acc[4][4];
#pragma unroll
        for (int i = 0; i < 4; i++)
#pragma unroll
            for (int j = 0; j < 4; j++) acc[i][j] = 0.0f;

#pragma unroll 4
        for (int d = 0; d < 64; d++) {
            const float4 kf = *(const float4*)(KP + d * PADL + (tx << 2));
            const float q0 = Qs[(ty * 4 + 0) * PADL + d];
            const float q1 = Qs[(ty * 4 + 1) * PADL + d];
            const float q2 = Qs[(ty * 4 + 2) * PADL + d];
            const float q3 = Qs[(ty * 4 + 3) * PADL + d];
            acc[0][0] += q0 * kf.x; acc[0][1] += q0 * kf.y; acc[0][2] += q0 * kf.z; acc[0][3] += q0 * kf.w;
            acc[1][0] += q1 * kf.x; acc[1][1] += q1 * kf.y; acc[1][2] += q1 * kf.z; acc[1][3] += q1 * kf.w;
            acc[2][0] += q2 * kf.x; acc[2][1] += q2 * kf.y; acc[2][2] += q2 * kf.z; acc[2][3] += q2 * kf.w;
            acc[3][0] += q3 * kf.x; acc[3][1] += q3 * kf.y; acc[3][2] += q3 * kf.z; acc[3][3] += q3 * kf.w;
        }

        if (kt == qt) {   // causal mask, diagonal tile only
#pragma unroll
            for (int i = 0; i < 4; i++)
#pragma unroll
                for (int j = 0; j < 4; j++)
                    if (tx * 4 + j > ty * 4 + i) acc[i][j] = -1e30f;
        }

        // Online softmax update (row stats across the 16 tx lanes; groups
        // of 16 never cross the 16-lane shuffle boundary)
        float p[4][4];
#pragma unroll
        for (int i = 0; i < 4; i++) {
            float rmax = fmaxf(fmaxf(acc[i][0], acc[i][1]), fmaxf(acc[i][2], acc[i][3]));
            rmax = fmaxf(rmax, __shfl_xor_sync(0xffffffffu, rmax, 1));
            rmax = fmaxf(rmax, __shfl_xor_sync(0xffffffffu, rmax, 2));
            rmax = fmaxf(rmax, __shfl_xor_sync(0xffffffffu, rmax, 4));
            rmax = fmaxf(rmax, __shfl_xor_sync(0xffffffffu, rmax, 8));
            const float mn = fmaxf(m_i[i], rmax);
            const float al = __expf(m_i[i] - mn);
            float rs = 0.0f;
#pragma unroll
            for (int j = 0; j < 4; j++) {
                p[i][j] = __expf(acc[i][j] - mn);
                rs += p[i][j];
            }
            rs += __shfl_xor_sync(0xffffffffu, rs, 1);
            rs += __shfl_xor_sync(0xffffffffu, rs, 2);
            rs += __shfl_xor_sync(0xffffffffu, rs, 4);
            rs += __shfl_xor_sync(0xffffffffu, rs, 8);
            l_i[i] = l_i[i] * al + rs;
            m_i[i] = mn;
#pragma unroll
            for (int j = 0; j < 4; j++) O[i][j] *= al;
        }

        __syncthreads();   // all K^T reads done -> reuse buffer for P
#pragma unroll
        for (int i = 0; i < 4; i++)
            *(float4*)(KP + (ty * 4 + i) * PADL + (tx << 2)) =
                make_float4(p[i][0], p[i][1], p[i][2], p[i][3]);
        __syncthreads();

        // O[i][j] += sum_k P[4ty+i][k] * V[k][4tx+j]
#pragma unroll 4
        for (int k = 0; k < 64; k++) {
            const float4 vf = *(const float4*)(Vs + k * PADL + (tx << 2));
            const float p0 = KP[(ty * 4 + 0) * PADL + k];
            const float p1 = KP[(ty * 4 + 1) * PADL + k];
            const float p2 = KP[(ty * 4 + 2) * PADL + k];
            const float p3 = KP[(ty * 4 + 3) * PADL + k];
            O[0][0] += p0 * vf.x; O[0][1] += p0 * vf.y; O[0][2] += p0 * vf.z; O[0][3] += p0 * vf.w;
            O[1][0] += p1 * vf.x; O[1][1] += p1 * vf.y; O[1][2] += p1 * vf.z; O[1][3] += p1 * vf.w;
            O[2][0] += p2 * vf.x; O[2][1] += p2 * vf.y; O[2][2] += p2 * vf.z; O[2][3] += p2 * vf.w;
            O[3][0] += p3 * vf.x; O[3][1] += p3 * vf.y; O[3][2] += p3 * vf.z; O[3][3] += p3 * vf.w;
        }
    }

    // Epilogue: ctx[b][s][h*64+d] = O / l
    const int b = bh / N_HEADS_C;
    const int h = bh % N_HEADS_C;
#pragma unroll
    for (int i = 0; i < 4; i++) {
        const float inv = 1.0f / l_i[i];
        const int s = qt * 64 + ty * 4 + i;
        float4 o = make_float4(O[i][0] * inv, O[i][1] * inv, O[i][2] * inv, O[i][3] * inv);
        *(float4*)(g_ctx + ((size_t)(b * S_LEN + s)) * D_MODEL + h * HEAD_DIM + (tx << 2)) = o;
    }
}

// ---------------------------------------------------------------------------
// Output projection: ctx[8192,768] @ Wo[768,768] + bo -> out
// ---------------------------------------------------------------------------
__global__ __launch_bounds__(256)
void out_gemm_kernel(const float* __restrict__ Wo,
                     const float* __restrict__ bo,
                     float* __restrict__ out) {
    __shared__ float As[8][128];
    __shared__ float Bs[8][128];

    const int m0 = blockIdx.y * 128;
    const int n0 = blockIdx.x * 128;
    const int tid = threadIdx.x;
    const int tx = tid & 15, ty = tid >> 4;
    const int ar = tid >> 1, ac = (tid & 1) * 4;
    const int br = tid >> 5, bc = (tid & 31) * 4;

    float acc[8][8];
#pragma unroll
    for (int i = 0; i < 8; i++)
#pragma unroll
        for (int j = 0; j < 8; j++) acc[i][j] = 0.0f;

    for (int k0 = 0; k0 < D_MODEL; k0 += 8) {
        float4 av = *(const float4*)(g_ctx + (size_t)(m0 + ar) * D_MODEL + k0 + ac);
        As[ac + 0][ar] = av.x;
        As[ac + 1][ar] = av.y;
        As[ac + 2][ar] = av.z;
        As[ac + 3][ar] = av.w;
        float4 bv = *(const float4*)(Wo + (size_t)(k0 + br) * D_MODEL + n0 + bc);
        *(float4*)&Bs[br][bc] = bv;
        __syncthreads();
#pragma unroll
        for (int kk = 0; kk < 8; kk++) {
            float a[8], b[8];
            *(float4*)(a)     = *(const float4*)&As[kk][ty * 8];
            *(float4*)(a + 4) = *(const float4*)&As[kk][ty * 8 + 4];
            *(float4*)(b)     = *(const float4*)&Bs[kk][tx * 8];
            *(float4*)(b + 4) = *(const float4*)&Bs[kk][tx * 8 + 4];
#pragma unroll
            for (int i = 0; i < 8; i++)
#pragma unroll
                for (int j = 0; j < 8; j++) acc[i][j] += a[i] * b[j];
        }
        __syncthreads();
    }

#pragma unroll
    for (int i = 0; i < 8; i++) {
        const int m = m0 + ty * 8 + i;
#pragma unroll
        for (int j = 0; j < 8; j += 4) {
            const int n = n0 + tx * 8 + j;
            float4 bb = *(const float4*)(bo + n);
            float4 o = make_float4(acc[i][j] + bb.x, acc[i][j + 1] + bb.y,
                                   acc[i][j + 2] + bb.z, acc[i][j + 3] + bb.w);
            *(float4*)(out + (size_t)m * D_MODEL + n) = o;
        }
    }
}

// ---------------------------------------------------------------------------
extern "C" void kernel_launch(void* const* d_in, const int* in_sizes, int n_in,
                              void* d_out, int out_size) {
    const float* x  = (const float*)d_in[0];
    const float* Wq = (const float*)d_in[1];
    const float* Wk = (const float*)d_in[2];
    const float* Wv = (const float*)d_in[3];
    const float* Wo = (const float*)d_in[4];
    const float* bo = (const float*)d_in[5];
    float* out = (float*)d_out;

    // 1) QKV projections
    qkv_gemm_kernel<<<dim3(D_MODEL / 128, N_TOK / 128, 3), 256>>>(x, Wq, Wk, Wv);

    // 2) Causal flash attention (52224 B dynamic smem -> needs opt-in; the
    //    attribute set is idempotent and not a stream op, safe under capture)
    const int attn_smem = 3 * 64 * PADL * (int)sizeof(float);
    cudaFuncSetAttribute(attn_kernel, cudaFuncAttributeMaxDynamicSharedMemorySize, attn_smem);
    attn_kernel<<<dim3(S_LEN / 64, BATCH * N_HEADS_C), 256, attn_smem>>>();

    // 3) Output projection + bias
    out_gemm_kernel<<<dim3(D_MODEL / 128, N_TOK / 128), 256>>>(Wo, bo, out);
}

// round 4
// speedup vs baseline: 1.8749x; 1.8749x over previous
#include <cuda_runtime.h>
#include <cuda_bf16.h>
#include <cstdint>

#define D_MODEL   768
#define N_HEADS_C 12
#define HEAD_DIM  64
#define S_LEN     4096
#define BATCH     2
#define N_TOK     (BATCH * S_LEN)     // 8192

// Scratch (allocation-free rule: __device__ globals)
__device__ float g_Q[BATCH * N_HEADS_C * S_LEN * HEAD_DIM];
__device__ float g_K[BATCH * N_HEADS_C * S_LEN * HEAD_DIM];
__device__ float g_V[BATCH * N_HEADS_C * S_LEN * HEAD_DIM];
__device__ float g_ctx[N_TOK * D_MODEL];

// ---------------------------------------------------------------------------
// mma.sync tf32 helpers (arch-agnostic PTX; works on compute_103)
// ---------------------------------------------------------------------------
__device__ __forceinline__ uint32_t f2tf(float f) {
    uint32_t r;
    asm("cvt.rna.tf32.f32 %0, %1;" : "=r"(r) : "f"(f));
    return r;
}

__device__ __forceinline__ void mma_tf32(float* d, const uint32_t* a, const uint32_t* b) {
    asm volatile(
        "mma.sync.aligned.m16n8k8.row.col.f32.tf32.tf32.f32 "
        "{%0,%1,%2,%3}, {%4,%5,%6,%7}, {%8,%9}, {%0,%1,%2,%3};"
        : "+f"(d[0]), "+f"(d[1]), "+f"(d[2]), "+f"(d[3])
        : "r"(a[0]), "r"(a[1]), "r"(a[2]), "r"(a[3]), "r"(b[0]), "r"(b[1]));
}

// ===========================================================================
// Projection GEMM: X[8192,768] @ W[768,768], 128x128 tile, 256 thr (8 warps),
// warp grid 2(m) x 4(n), each warp 64x32 via m16n8k8 tiles. K chunks of 32.
// ===========================================================================
#define KC    32
#define PAD_G 36

__device__ __forceinline__ void gemm_tile_mma(const float* __restrict__ X,
                                              const float* __restrict__ W,
                                              int m0, int n0,
                                              float acc[4][4][4],
                                              uint32_t (*As)[PAD_G],
                                              uint32_t (*Bs)[PAD_G]) {
    const int tid = threadIdx.x;
    const int lane = tid & 31, wid = tid >> 5;
    const int g = lane >> 2, q = lane & 3;
    const int wm = wid >> 2, wn = wid & 3;

#pragma unroll
    for (int mt = 0; mt < 4; mt++)
#pragma unroll
        for (int nt = 0; nt < 4; nt++)
#pragma unroll
            for (int e = 0; e < 4; e++) acc[mt][nt][e] = 0.0f;

    const int ar = tid >> 1, acb = (tid & 1) * 16;     // A: row, col-base (2 thr/row)
    const int bk = tid & 31, bn = (tid >> 5) * 16;     // B: k = lane, 16 n per thread

    for (int k0 = 0; k0 < D_MODEL; k0 += KC) {
        __syncthreads();
        // A tile -> As[m][k]  (row-major, tf32)
        const float* xa = X + (size_t)(m0 + ar) * D_MODEL + k0 + acb;
#pragma unroll
        for (int i = 0; i < 4; i++) {
            float4 v = *(const float4*)(xa + 4 * i);
            uint4 u = make_uint4(f2tf(v.x), f2tf(v.y), f2tf(v.z), f2tf(v.w));
            *(uint4*)&As[ar][acb + 4 * i] = u;
        }
        // B tile -> Bs[n][k]  (W transposed, tf32). Conflict-free: k = lane.
        const float* wb = W + (size_t)(k0 + bk) * D_MODEL + n0 + bn;
#pragma unroll
        for (int i = 0; i < 4; i++) {
            float4 v = *(const float4*)(wb + 4 * i);
            Bs[bn + 4 * i + 0][bk] = f2tf(v.x);
            Bs[bn + 4 * i + 1][bk] = f2tf(v.y);
            Bs[bn + 4 * i + 2][bk] = f2tf(v.z);
            Bs[bn + 4 * i + 3][bk] = f2tf(v.w);
        }
        __syncthreads();

#pragma unroll
        for (int ks = 0; ks < 4; ks++) {
            const int kc = ks * 8 + q;
            uint32_t a[4][4], b[4][2];
#pragma unroll
            for (int mt = 0; mt < 4; mt++) {
                const int r = wm * 64 + mt * 16 + g;
                a[mt][0] = As[r][kc];
                a[mt][1] = As[r + 8][kc];
                a[mt][2] = As[r][kc + 4];
                a[mt][3] = As[r + 8][kc + 4];
            }
#pragma unroll
            for (int nt = 0; nt < 4; nt++) {
                const int n = wn * 32 + nt * 8 + g;
                b[nt][0] = Bs[n][kc];
                b[nt][1] = Bs[n][kc + 4];
            }
#pragma unroll
            for (int mt = 0; mt < 4; mt++)
#pragma unroll
                for (int nt = 0; nt < 4; nt++)
                    mma_tf32(acc[mt][nt], a[mt], b[nt]);
        }
    }
}

// QKV: scatter epilogue into [B,H,S,Dh]; z selects Wq/Wk/Wv
__global__ __launch_bounds__(256)
void qkv_gemm_mma(const float* __restrict__ x,
                  const float* __restrict__ Wq,
                  const float* __restrict__ Wk,
                  const float* __restrict__ Wv) {
    __shared__ uint32_t As[128][PAD_G];
    __shared__ uint32_t Bs[128][PAD_G];
    const int z = blockIdx.z;
    const float* W = (z == 0) ? Wq : ((z == 1) ? Wk : Wv);
    float* dst = (z == 0) ? g_Q : ((z == 1) ? g_K : g_V);
    const int n0 = blockIdx.x * 128;
    const int m0 = blockIdx.y * 128;

    float acc[4][4][4];
    gemm_tile_mma(x, W, m0, n0, acc, As, Bs);

    const int lane = threadIdx.x & 31, wid = threadIdx.x >> 5;
    const int g = lane >> 2, q = lane & 3;
    const int wm = wid >> 2, wn = wid & 3;
#pragma unroll
    for (int mt = 0; mt < 4; mt++) {
        const int m_lo = m0 + wm * 64 + mt * 16 + g;
#pragma unroll
        for (int nt = 0; nt < 4; nt++) {
            const int c = n0 + wn * 32 + nt * 8 + 2 * q;
            const int h = c >> 6, d = c & 63;
#pragma unroll
            for (int half = 0; half < 2; half++) {
                const int m = m_lo + half * 8;
                const int b = m >> 12, s = m & (S_LEN - 1);
                float2 o = make_float2(acc[mt][nt][half * 2], acc[mt][nt][half * 2 + 1]);
                *(float2*)(dst + ((size_t)((b * N_HEADS_C + h) * S_LEN + s)) * HEAD_DIM + d) = o;
            }
        }
    }
}

// Output projection: ctx @ Wo + bo -> out
__global__ __launch_bounds__(256)
void out_gemm_mma(const float* __restrict__ Wo,
                  const float* __restrict__ bo,
                  float* __restrict__ out) {
    __shared__ uint32_t As[128][PAD_G];
    __shared__ uint32_t Bs[128][PAD_G];
    const int n0 = blockIdx.x * 128;
    const int m0 = blockIdx.y * 128;

    float acc[4][4][4];
    gemm_tile_mma(g_ctx, Wo, m0, n0, acc, As, Bs);

    const int lane = threadIdx.x & 31, wid = threadIdx.x >> 5;
    const int g = lane >> 2, q = lane & 3;
    const int wm = wid >> 2, wn = wid & 3;
#pragma unroll
    for (int mt = 0; mt < 4; mt++) {
        const int m_lo = m0 + wm * 64 + mt * 16 + g;
#pragma unroll
        for (int nt = 0; nt < 4; nt++) {
            const int c = n0 + wn * 32 + nt * 8 + 2 * q;
            const float2 bb = *(const float2*)(bo + c);
#pragma unroll
            for (int half = 0; half < 2; half++) {
                const int m = m_lo + half * 8;
                float2 o = make_float2(acc[mt][nt][half * 2] + bb.x,
                                       acc[mt][nt][half * 2 + 1] + bb.y);
                *(float2*)(out + (size_t)m * D_MODEL + c) = o;
            }
        }
    }
}

// ===========================================================================
// Flash attention via mma.sync tf32. 64x64 q-tile, 128 threads (4 warps),
// warp w owns q-rows [w*16, w*16+16). Scores & PV are m16n8k8 mma.
// Smem (uint32 tf32 words): Qs[64][68] | Ks[64][68] | Ps[64][68] | Vs[64][72]
// ===========================================================================
#define QS_STR 68
#define VS_STR 72
#define ATTN_SMEM ((3 * 64 * QS_STR + 64 * VS_STR) * 4)

__global__ __launch_bounds__(128)
void attn_mma() {
    extern __shared__ uint32_t sm[];
    uint32_t* Qs = sm;
    uint32_t* Ks = Qs + 64 * QS_STR;
    uint32_t* Ps = Ks + 64 * QS_STR;
    uint32_t* Vs = Ps + 64 * QS_STR;

    const int tid = threadIdx.x;
    const int lane = tid & 31, wid = tid >> 5;
    const int g = lane >> 2, q = lane & 3;
    const int r0 = wid * 16 + g;          // tile-local q-row (and r0+8)

    const int bh = blockIdx.y;
    const int qt = (int)gridDim.x - 1 - (int)blockIdx.x;   // heavy tiles first
    const size_t base = (size_t)bh * S_LEN * HEAD_DIM;
    const float* Qg = g_Q + base + (size_t)qt * 64 * HEAD_DIM;
    const float* Kg = g_K + base;
    const float* Vg = g_V + base;

    // Load Q tile (scale 1/8 folded in; exact power-of-2 scaling, then tf32 RN)
    {
        const int lr = tid >> 1, lcb = (tid & 1) * 32;
        const float* src = Qg + lr * HEAD_DIM + lcb;
#pragma unroll
        for (int i = 0; i < 8; i++) {
            float4 v = *(const float4*)(src + 4 * i);
            uint4 u = make_uint4(f2tf(v.x * 0.125f), f2tf(v.y * 0.125f),
                                 f2tf(v.z * 0.125f), f2tf(v.w * 0.125f));
            *(uint4*)&Qs[lr * QS_STR + lcb + 4 * i] = u;
        }
    }

    float o[8][4];
#pragma unroll
    for (int nt = 0; nt < 8; nt++)
#pragma unroll
        for (int e = 0; e < 4; e++) o[nt][e] = 0.0f;
    float m_0 = -1e30f, m_1 = -1e30f, l_0 = 0.0f, l_1 = 0.0f;

    for (int kt = 0; kt <= qt; kt++) {
        __syncthreads();   // prior iteration's Ks/Vs reads complete
        {
            const int lr = tid >> 1, lcb = (tid & 1) * 32;
            const float* ksrc = Kg + (size_t)kt * 64 * HEAD_DIM + lr * HEAD_DIM + lcb;
            const float* vsrc = Vg + (size_t)kt * 64 * HEAD_DIM + lr * HEAD_DIM + lcb;
#pragma unroll
            for (int i = 0; i < 8; i++) {
                float4 kv = *(const float4*)(ksrc + 4 * i);
                *(uint4*)&Ks[lr * QS_STR + lcb + 4 * i] =
                    make_uint4(f2tf(kv.x), f2tf(kv.y), f2tf(kv.z), f2tf(kv.w));
                float4 vv = *(const float4*)(vsrc + 4 * i);
                *(uint4*)&Vs[lr * VS_STR + lcb + 4 * i] =
                    make_uint4(f2tf(vv.x), f2tf(vv.y), f2tf(vv.z), f2tf(vv.w));
            }
        }
        __syncthreads();

        // ---- Scores S = Q @ K^T (tile 64x64) ----
        float sc[8][4];
#pragma unroll
        for (int nt = 0; nt < 8; nt++)
#pragma unroll
            for (int e = 0; e < 4; e++) sc[nt][e] = 0.0f;

#pragma unroll
        for (int ks = 0; ks < 8; ks++) {
            const int kc = ks * 8 + q;
            uint32_t a[4];
            a[0] = Qs[r0 * QS_STR + kc];
            a[1] = Qs[(r0 + 8) * QS_STR + kc];
            a[2] = Qs[r0 * QS_STR + kc + 4];
            a[3] = Qs[(r0 + 8) * QS_STR + kc + 4];
#pragma unroll
            for (int nt = 0; nt < 8; nt++) {
                uint32_t b[2];
                b[0] = Ks[(nt * 8 + g) * QS_STR + kc];
                b[1] = Ks[(nt * 8 + g) * QS_STR + kc + 4];
                mma_tf32(sc[nt], a, b);
            }
        }

        if (kt == qt) {   // causal mask (diagonal tile): col > row -> -inf
#pragma unroll
            for (int nt = 0; nt < 8; nt++) {
                const int c = nt * 8 + 2 * q;
                if (c + 0 > r0) sc[nt][0] = -1e30f;
                if (c + 1 > r0) sc[nt][1] = -1e30f;
                if (c + 0 > r0 + 8) sc[nt][2] = -1e30f;
                if (c + 1 > r0 + 8) sc[nt][3] = -1e30f;
            }
        }

        // ---- Online softmax (two rows per thread, reduce across quad) ----
        float rm0 = -1e30f, rm1 = -1e30f;
#pragma unroll
        for (int nt = 0; nt < 8; nt++) {
            rm0 = fmaxf(rm0, fmaxf(sc[nt][0], sc[nt][1]));
            rm1 = fmaxf(rm1, fmaxf(sc[nt][2], sc[nt][3]));
        }
        rm0 = fmaxf(rm0, __shfl_xor_sync(0xffffffffu, rm0, 1));
        rm0 = fmaxf(rm0, __shfl_xor_sync(0xffffffffu, rm0, 2));
        rm1 = fmaxf(rm1, __shfl_xor_sync(0xffffffffu, rm1, 1));
        rm1 = fmaxf(rm1, __shfl_xor_sync(0xffffffffu, rm1, 2));

        const float mn0 = fmaxf(m_0, rm0), mn1 = fmaxf(m_1, rm1);
        const float al0 = __expf(m_0 - mn0), al1 = __expf(m_1 - mn1);
        float rs0 = 0.0f, rs1 = 0.0f;
#pragma unroll
        for (int nt = 0; nt < 8; nt++) {
            sc[nt][0] = __expf(sc[nt][0] - mn0);
            sc[nt][1] = __expf(sc[nt][1] - mn0);
            sc[nt][2] = __expf(sc[nt][2] - mn1);
            sc[nt][3] = __expf(sc[nt][3] - mn1);
            rs0 += sc[nt][0] + sc[nt][1];
            rs1 += sc[nt][2] + sc[nt][3];
        }
        rs0 += __shfl_xor_sync(0xffffffffu, rs0, 1);
        rs0 += __shfl_xor_sync(0xffffffffu, rs0, 2);
        rs1 += __shfl_xor_sync(0xffffffffu, rs1, 1);
        rs1 += __shfl_xor_sync(0xffffffffu, rs1, 2);
        l_0 = l_0 * al0 + rs0;  m_0 = mn0;
        l_1 = l_1 * al1 + rs1;  m_1 = mn1;

#pragma unroll
        for (int nt = 0; nt < 8; nt++) {
            o[nt][0] *= al0; o[nt][1] *= al0;
            o[nt][2] *= al1; o[nt][3] *= al1;
        }

        // ---- P -> smem (C-layout write; re-read as A-fragments, same warp rows) ----
#pragma unroll
        for (int nt = 0; nt < 8; nt++) {
            const int c = nt * 8 + 2 * q;
            *(uint2*)&Ps[r0 * QS_STR + c]       = make_uint2(f2tf(sc[nt][0]), f2tf(sc[nt][1]));
            *(uint2*)&Ps[(r0 + 8) * QS_STR + c] = make_uint2(f2tf(sc[nt][2]), f2tf(sc[nt][3]));
        }
        __syncwarp();

        // ---- O += P @ V ----
#pragma unroll
        for (int ks = 0; ks < 8; ks++) {
            const int kc = ks * 8 + q;
            uint32_t pa[4];
            pa[0] = Ps[r0 * QS_STR + kc];
            pa[1] = Ps[(r0 + 8) * QS_STR + kc];
            pa[2] = Ps[r0 * QS_STR + kc + 4];
            pa[3] = Ps[(r0 + 8) * QS_STR + kc + 4];
#pragma unroll
            for (int nt = 0; nt < 8; nt++) {
                uint32_t b[2];
                b[0] = Vs[kc * VS_STR + nt * 8 + g];
                b[1] = Vs[(kc + 4) * VS_STR + nt * 8 + g];
                mma_tf32(o[nt], pa, b);
            }
        }
    }

    // ---- Epilogue: normalize, write ctx[b][s][h*64+d] ----
    const int b = bh / N_HEADS_C;
    const int h = bh % N_HEADS_C;
    const float inv0 = 1.0f / l_0, inv1 = 1.0f / l_1;
    const int s0 = qt * 64 + r0, s1 = s0 + 8;
    float* out0 = g_ctx + ((size_t)(b * S_LEN + s0)) * D_MODEL + h * HEAD_DIM;
    float* out1 = g_ctx + ((size_t)(b * S_LEN + s1)) * D_MODEL + h * HEAD_DIM;
#pragma unroll
    for (int nt = 0; nt < 8; nt++) {
        const int c = nt * 8 + 2 * q;
        *(float2*)(out0 + c) = make_float2(o[nt][0] * inv0, o[nt][1] * inv0);
        *(float2*)(out1 + c) = make_float2(o[nt][2] * inv1, o[nt][3] * inv1);
    }
}

// ---------------------------------------------------------------------------
extern "C" void kernel_launch(void* const* d_in, const int* in_sizes, int n_in,
                              void* d_out, int out_size) {
    const float* x  = (const float*)d_in[0];
    const float* Wq = (const float*)d_in[1];
    const float* Wk = (const float*)d_in[2];
    const float* Wv = (const float*)d_in[3];
    const float* Wo = (const float*)d_in[4];
    const float* bo = (const float*)d_in[5];
    float* out = (float*)d_out;

    // 1) QKV projections (tf32 mma.sync)
    qkv_gemm_mma<<<dim3(D_MODEL / 128, N_TOK / 128, 3), 256>>>(x, Wq, Wk, Wv);

    // 2) Causal flash attention (tf32 mma.sync)
    cudaFuncSetAttribute(attn_mma, cudaFuncAttributeMaxDynamicSharedMemorySize, ATTN_SMEM);
    attn_mma<<<dim3(S_LEN / 64, BATCH * N_HEADS_C), 128, ATTN_SMEM>>>();

    // 3) Output projection + bias (tf32 mma.sync)
    out_gemm_mma<<<dim3(D_MODEL / 128, N_TOK / 128), 256>>>(Wo, bo, out);
}